// round 7
// baseline (speedup 1.0000x reference)
#include <cuda_runtime.h>
#include <cuda_bf16.h>

#define NB 4096
#define NS 256
#define ND 32

// histogram layout in smem: job[11] @0, rep[34] @11, place[19] @45, add[31] @64 -> 95 ints
#define H_JOB 0
#define H_REP 11
#define H_PLACE 45
#define H_ADD 64
#define H_TOT 95

__global__ __launch_bounds__(256)
void fused_kernel(const float* __restrict__ cont_p, const float* __restrict__ cont_c,
                  const int* __restrict__ cat_p, const int* __restrict__ cat_c,
                  const int* __restrict__ lengths,
                  const float* __restrict__ w_p1, const float* __restrict__ b_p1,
                  const float* __restrict__ w_p2, const float* __restrict__ b_p2,
                  const float* __restrict__ w_c1, const float* __restrict__ b_c1,
                  const float* __restrict__ w_c2, const float* __restrict__ b_c2,
                  const float* __restrict__ eg, const float* __restrict__ ek,
                  const float* __restrict__ epr, const float* __restrict__ ejob,
                  const float* __restrict__ erep, const float* __restrict__ epl,
                  const float* __restrict__ eadd,
                  const float* __restrict__ w_fc1, const float* __restrict__ b_fc1,
                  const float* __restrict__ w_fc2, const float* __restrict__ b_fc2,
                  float* __restrict__ out)
{
    const int b = blockIdx.x;
    const int tid = threadIdx.x;
    const int lane = tid & 31;
    const int w = tid >> 5;

    // raw staged inputs for this batch
    __shared__ float4 s_cp4[192];   // cont_p: up to 768 floats
    __shared__ float4 s_cc4[128];   // cont_c: up to 512 floats
    __shared__ int4   s_vp4[320];   // cat_p:  up to 1280 ints
    __shared__ int4   s_vc4[128];   // cat_c:  up to 512 ints
    __shared__ int s_hist[H_TOT];
    __shared__ unsigned s_binpack;  // gender | korean<<10 | primary<<20
    __shared__ float s_red[2][8][32];
    __shared__ float s_apsum[32];
    __shared__ float s_acsum[32];
    __shared__ float s_rep[32];     // rep-table partial (split tail)
    __shared__ float s_pool[128];
    __shared__ float s_h1[64];

    if (tid < H_TOT) s_hist[tid] = 0;
    if (tid == 0) s_binpack = 0u;

    const int len = lengths[b];

    // per-lane weights for the first linear layers (hoisted)
    const float wa0 = w_p1[lane], wa1 = w_p1[32 + lane], wa2 = w_p1[64 + lane], ba = b_p1[lane];
    const float wb0 = w_c1[lane], wb1 = w_c1[32 + lane], bb = b_c1[lane];

    // ---- Phase A: exact-length vectorized staging (all coalesced 16B loads) ----
    {
        const int ncp = (3 * len + 3) >> 2;   // <= 192
        const int ncc = (2 * len + 3) >> 2;   // <= 128
        const int nvp = (5 * len + 3) >> 2;   // <= 320
        const int nvc = (2 * len + 3) >> 2;   // <= 128

        const float4* gcp = (const float4*)(cont_p + b * (NS * 3));
        const float4* gcc = (const float4*)(cont_c + b * (NS * 2));
        const int4*   gvp = (const int4*)(cat_p + b * (NS * 5));
        const int4*   gvc = (const int4*)(cat_c + b * (NS * 2));

        if (tid < ncp) s_cp4[tid] = gcp[tid];
        if (tid < ncc) s_cc4[tid] = gcc[tid];
        if (tid < nvp) s_vp4[tid] = gvp[tid];
        if (tid + 256 < nvp) s_vp4[tid + 256] = gvp[tid + 256];
        if (tid < nvc) s_vc4[tid] = gvc[tid];
    }
    __syncthreads();

    // ---- Phase A2: thread-per-token histograms from smem ----
    {
        const int t = tid;
        const unsigned act = __ballot_sync(0xffffffffu, t < len);
        if (t < len) {
            const int* sp = (const int*)s_vp4;
            const int* sc = (const int*)s_vc4;
            const int v0 = sp[t * 5 + 0];
            const int v1 = sp[t * 5 + 1];
            const int v2 = sp[t * 5 + 2];
            const int v3 = sp[t * 5 + 3];
            const int v4 = sp[t * 5 + 4];
            const int c0 = sc[t * 2 + 0];
            const int c1 = sc[t * 2 + 1];

            const unsigned packed = (unsigned)v0 | ((unsigned)v1 << 10) | ((unsigned)v2 << 20);
            const unsigned wsum = __reduce_add_sync(act, packed);
            if (lane == 0) atomicAdd(&s_binpack, wsum);

            {
                unsigned mm = __match_any_sync(act, v3);
                if (lane == __ffs(mm) - 1) atomicAdd(&s_hist[H_JOB + v3], __popc(mm));
            }
            {
                unsigned mm = __match_any_sync(act, v4);
                if (lane == __ffs(mm) - 1) atomicAdd(&s_hist[H_REP + v4], __popc(mm));
            }
            {
                unsigned mm = __match_any_sync(act, c0);
                if (lane == __ffs(mm) - 1) atomicAdd(&s_hist[H_PLACE + c0], __popc(mm));
            }
            {
                unsigned mm = __match_any_sync(act, c1);
                if (lane == __ffs(mm) - 1) atomicAdd(&s_hist[H_ADD + c1], __popc(mm));
            }
        }
    }

    // ---- Phase B: lane = output dim, 8 warps split tokens (raw-layout reads) ----
    const float* scp = (const float*)s_cp4;
    const float* scc = (const float*)s_cc4;

    float ap_acc = 0.f, ac_acc = 0.f;
    #pragma unroll 4
    for (int t = w; t < len; t += 8) {
        const float x0 = scp[t * 3 + 0];
        const float x1 = scp[t * 3 + 1];
        const float x2 = scp[t * 3 + 2];
        const float y0 = scc[t * 2 + 0];
        const float y1 = scc[t * 2 + 1];
        float ap = fmaf(x2, wa2, fmaf(x1, wa1, fmaf(x0, wa0, ba)));
        ap_acc += fmaxf(ap, 0.f);
        float ac = fmaf(y1, wb1, fmaf(y0, wb0, bb));
        ac_acc += fmaxf(ac, 0.f);
    }

    s_red[0][w][lane] = ap_acc;
    s_red[1][w][lane] = ac_acc;
    __syncthreads();

    if (tid < 32) {
        float s = 0.f;
        #pragma unroll
        for (int i = 0; i < 8; i++) s += s_red[0][i][tid];
        s_apsum[tid] = s;
    } else if (tid < 64) {
        const int l = tid - 32;
        float s = 0.f;
        #pragma unroll
        for (int i = 0; i < 8; i++) s += s_red[1][i][l];
        s_acsum[l] = s;
    }
    __syncthreads();

    // ---- tail: compute pooled[128] (rep table split to threads 128-159) ----
    const float flen = (float)len;
    const float inv_len = 1.0f / flen;

    float e1 = 0.f;   // only meaningful for tid<32
    if (tid < 32) {
        const int dd = tid;
        const unsigned bp = s_binpack;
        const float n1g = (float)(bp & 1023u);
        const float n1k = (float)((bp >> 10) & 1023u);
        const float n1p = (float)((bp >> 20) & 1023u);
        e1 = (flen - n1g) * eg[dd]  + n1g * eg[32 + dd]
           + (flen - n1k) * ek[dd]  + n1k * ek[32 + dd]
           + (flen - n1p) * epr[dd] + n1p * epr[32 + dd];
        #pragma unroll
        for (int v = 0; v < 11; v++) e1 = fmaf((float)s_hist[H_JOB + v], ejob[v * 32 + dd], e1);
    } else if (tid < 64) {
        const int dd = tid - 32;
        float e = 0.f;
        #pragma unroll
        for (int v = 0; v < 19; v++) e = fmaf((float)s_hist[H_PLACE + v], epl[v * 32 + dd], e);
        #pragma unroll
        for (int v = 0; v < 31; v++) e = fmaf((float)s_hist[H_ADD + v], eadd[v * 32 + dd], e);
        s_pool[32 + dd] = e * (inv_len * 0.5f);
    } else if (tid < 96) {
        const int dd = tid - 64;
        float s = 0.f;
        #pragma unroll
        for (int k = 0; k < 32; k++) s = fmaf(s_apsum[k], w_p2[k * 32 + dd], s);
        s_pool[64 + dd] = fmaf(s, inv_len, b_p2[dd]);
    } else if (tid < 128) {
        const int dd = tid - 96;
        float s = 0.f;
        #pragma unroll
        for (int k = 0; k < 32; k++) s = fmaf(s_acsum[k], w_c2[k * 32 + dd], s);
        s_pool[96 + dd] = fmaf(s, inv_len, b_c2[dd]);
    } else if (tid < 160) {
        const int dd = tid - 128;
        float e = 0.f;
        #pragma unroll
        for (int v = 0; v < 34; v++) e = fmaf((float)s_hist[H_REP + v], erep[v * 32 + dd], e);
        s_rep[dd] = e;
    }
    __syncthreads();

    if (tid < 32) {
        s_pool[tid] = (e1 + s_rep[tid]) * (inv_len * 0.2f);
    }
    __syncthreads();

    // ---- fused head: fc1 (128->64, relu), 256 threads = 64 outputs x 4-way d-split ----
    {
        const int j = tid >> 2;     // 0..63 output col
        const int c = tid & 3;      // d-chunk
        float s = 0.f;
        const int d0 = c * 32;
        #pragma unroll
        for (int i = 0; i < 32; i++)
            s = fmaf(s_pool[d0 + i], w_fc1[(d0 + i) * 64 + j], s);
        s += __shfl_xor_sync(0xffffffffu, s, 1);
        s += __shfl_xor_sync(0xffffffffu, s, 2);
        if (c == 0) s_h1[j] = fmaxf(s + b_fc1[j], 0.f);
    }
    __syncthreads();

    // ---- fc2 (64->2, relu): warp 0 -> out0, warp 1 -> out1, warp reduce ----
    if (tid < 64) {
        const int o = w;   // 0 or 1
        float s = fmaf(s_h1[lane], w_fc2[lane * 2 + o],
                       s_h1[lane + 32] * w_fc2[(lane + 32) * 2 + o]);
        s += __shfl_xor_sync(0xffffffffu, s, 16);
        s += __shfl_xor_sync(0xffffffffu, s, 8);
        s += __shfl_xor_sync(0xffffffffu, s, 4);
        s += __shfl_xor_sync(0xffffffffu, s, 2);
        s += __shfl_xor_sync(0xffffffffu, s, 1);
        if (lane == 0) out[b * 2 + o] = fmaxf(s + b_fc2[o], 0.f);
    }
}

extern "C" void kernel_launch(void* const* d_in, const int* in_sizes, int n_in,
                              void* d_out, int out_size)
{
    const float* cont_p = (const float*)d_in[0];
    const float* cont_c = (const float*)d_in[1];
    const int*   cat_p  = (const int*)d_in[2];
    const int*   cat_c  = (const int*)d_in[3];
    const int*   lengths= (const int*)d_in[4];
    const float* w_p1   = (const float*)d_in[5];
    const float* b_p1   = (const float*)d_in[6];
    const float* w_p2   = (const float*)d_in[7];
    const float* b_p2   = (const float*)d_in[8];
    const float* w_c1   = (const float*)d_in[9];
    const float* b_c1   = (const float*)d_in[10];
    const float* w_c2   = (const float*)d_in[11];
    const float* b_c2   = (const float*)d_in[12];
    const float* eg     = (const float*)d_in[13];
    const float* ek     = (const float*)d_in[14];
    const float* epr    = (const float*)d_in[15];
    const float* ejob   = (const float*)d_in[16];
    const float* erep   = (const float*)d_in[17];
    const float* epl    = (const float*)d_in[18];
    const float* eadd   = (const float*)d_in[19];
    const float* w_fc1  = (const float*)d_in[20];
    const float* b_fc1  = (const float*)d_in[21];
    const float* w_fc2  = (const float*)d_in[22];
    const float* b_fc2  = (const float*)d_in[23];
    float* out = (float*)d_out;

    fused_kernel<<<NB, 256>>>(cont_p, cont_c, cat_p, cat_c, lengths,
                              w_p1, b_p1, w_p2, b_p2, w_c1, b_c1, w_c2, b_c2,
                              eg, ek, epr, ejob, erep, epl, eadd,
                              w_fc1, b_fc1, w_fc2, b_fc2, out);
}

// round 8
// speedup vs baseline: 1.5544x; 1.5544x over previous
#include <cuda_runtime.h>
#include <cuda_bf16.h>

#define NB 4096
#define NS 256

// histogram layout in smem: job[11] @0, rep[34] @11, place[19] @45, add[31] @64 -> 95 ints
#define H_JOB 0
#define H_REP 11
#define H_PLACE 45
#define H_ADD 64
#define H_TOT 95

__global__ __launch_bounds__(256)
void fused_kernel(const float* __restrict__ cont_p, const float* __restrict__ cont_c,
                  const int* __restrict__ cat_p, const int* __restrict__ cat_c,
                  const int* __restrict__ lengths,
                  const float* __restrict__ w_p1, const float* __restrict__ b_p1,
                  const float* __restrict__ w_p2, const float* __restrict__ b_p2,
                  const float* __restrict__ w_c1, const float* __restrict__ b_c1,
                  const float* __restrict__ w_c2, const float* __restrict__ b_c2,
                  const float* __restrict__ eg, const float* __restrict__ ek,
                  const float* __restrict__ epr, const float* __restrict__ ejob,
                  const float* __restrict__ erep, const float* __restrict__ epl,
                  const float* __restrict__ eadd,
                  const float* __restrict__ w_fc1, const float* __restrict__ b_fc1,
                  const float* __restrict__ w_fc2, const float* __restrict__ b_fc2,
                  float* __restrict__ out)
{
    const int b = blockIdx.x;
    const int tid = threadIdx.x;
    const int lane = tid & 31;
    const int w = tid >> 5;

    __shared__ float4 s_t4[NS];     // {x0,x1,x2,y0} per token
    __shared__ float s_y1[NS];
    __shared__ int s_hist[H_TOT];
    __shared__ unsigned s_binpack;  // gender | korean<<10 | primary<<20
    __shared__ float s_red[2][8][32];
    __shared__ float s_apsum[32];
    __shared__ float s_acsum[32];
    __shared__ float s_rep[32];     // rep-table partial (split tail)
    __shared__ float s_pool[128];
    __shared__ float s_part[4][64];
    __shared__ float s_h1[64];

    if (tid < H_TOT) s_hist[tid] = 0;
    if (tid == 0) s_binpack = 0u;
    __syncthreads();

    const int len = lengths[b];
    const int rowbase = b * NS;

    // per-lane weights for the first linear layers
    const float wa0 = w_p1[lane], wa1 = w_p1[32 + lane], wa2 = w_p1[64 + lane], ba = b_p1[lane];
    const float wb0 = w_c1[lane], wb1 = w_c1[32 + lane], bb = b_c1[lane];

    // ---- Phase A: thread-per-token coalesced staging + warp-aggregated histograms ----
    {
        const int t = tid;
        const unsigned act = __ballot_sync(0xffffffffu, t < len);
        if (t < len) {
            const int r = rowbase + t;
            const float x0 = cont_p[r * 3 + 0];
            const float x1 = cont_p[r * 3 + 1];
            const float x2 = cont_p[r * 3 + 2];
            const float y0 = cont_c[r * 2 + 0];
            const float y1 = cont_c[r * 2 + 1];
            s_t4[t] = make_float4(x0, x1, x2, y0);
            s_y1[t] = y1;

            const int v0 = cat_p[r * 5 + 0];
            const int v1 = cat_p[r * 5 + 1];
            const int v2 = cat_p[r * 5 + 2];
            const int v3 = cat_p[r * 5 + 3];
            const int v4 = cat_p[r * 5 + 4];
            const int c0 = cat_c[r * 2 + 0];
            const int c1 = cat_c[r * 2 + 1];

            // binary vocab columns: packed warp reduce
            const unsigned packed = (unsigned)v0 | ((unsigned)v1 << 10) | ((unsigned)v2 << 20);
            const unsigned wsum = __reduce_add_sync(act, packed);
            if (lane == 0) atomicAdd(&s_binpack, wsum);

            // warp-aggregated histogram adds
            {
                unsigned mm = __match_any_sync(act, v3);
                if (lane == __ffs(mm) - 1) atomicAdd(&s_hist[H_JOB + v3], __popc(mm));
            }
            {
                unsigned mm = __match_any_sync(act, v4);
                if (lane == __ffs(mm) - 1) atomicAdd(&s_hist[H_REP + v4], __popc(mm));
            }
            {
                unsigned mm = __match_any_sync(act, c0);
                if (lane == __ffs(mm) - 1) atomicAdd(&s_hist[H_PLACE + c0], __popc(mm));
            }
            {
                unsigned mm = __match_any_sync(act, c1);
                if (lane == __ffs(mm) - 1) atomicAdd(&s_hist[H_ADD + c1], __popc(mm));
            }
        }
    }
    __syncthreads();

    // ---- Phase B: lane = output dim, 8 warps split tokens; 2 LDS/token ----
    float ap_acc = 0.f, ac_acc = 0.f;
    #pragma unroll 4
    for (int t = w; t < len; t += 8) {
        const float4 v = s_t4[t];
        const float y1 = s_y1[t];
        float ap = fmaf(v.z, wa2, fmaf(v.y, wa1, fmaf(v.x, wa0, ba)));
        ap_acc += fmaxf(ap, 0.f);
        float ac = fmaf(y1, wb1, fmaf(v.w, wb0, bb));
        ac_acc += fmaxf(ac, 0.f);
    }

    s_red[0][w][lane] = ap_acc;
    s_red[1][w][lane] = ac_acc;
    __syncthreads();

    if (tid < 32) {
        float s = 0.f;
        #pragma unroll
        for (int i = 0; i < 8; i++) s += s_red[0][i][tid];
        s_apsum[tid] = s;
    } else if (tid < 64) {
        const int l = tid - 32;
        float s = 0.f;
        #pragma unroll
        for (int i = 0; i < 8; i++) s += s_red[1][i][l];
        s_acsum[l] = s;
    }
    __syncthreads();

    // ---- tail: compute pooled[128] into smem (rep table split to threads 128-159) ----
    const float flen = (float)len;
    const float inv_len = 1.0f / flen;

    float e1 = 0.f;   // only meaningful for tid<32
    if (tid < 32) {
        const int dd = tid;
        const unsigned bp = s_binpack;
        const float n1g = (float)(bp & 1023u);
        const float n1k = (float)((bp >> 10) & 1023u);
        const float n1p = (float)((bp >> 20) & 1023u);
        e1 = (flen - n1g) * eg[dd]  + n1g * eg[32 + dd]
           + (flen - n1k) * ek[dd]  + n1k * ek[32 + dd]
           + (flen - n1p) * epr[dd] + n1p * epr[32 + dd];
        #pragma unroll
        for (int v = 0; v < 11; v++) e1 = fmaf((float)s_hist[H_JOB + v], ejob[v * 32 + dd], e1);
    } else if (tid < 64) {
        const int dd = tid - 32;
        float e = 0.f;
        #pragma unroll
        for (int v = 0; v < 19; v++) e = fmaf((float)s_hist[H_PLACE + v], epl[v * 32 + dd], e);
        #pragma unroll
        for (int v = 0; v < 31; v++) e = fmaf((float)s_hist[H_ADD + v], eadd[v * 32 + dd], e);
        s_pool[32 + dd] = e * (inv_len * 0.5f);
    } else if (tid < 96) {
        const int dd = tid - 64;
        float s = 0.f;
        #pragma unroll
        for (int k = 0; k < 32; k++) s = fmaf(s_apsum[k], w_p2[k * 32 + dd], s);
        s_pool[64 + dd] = fmaf(s, inv_len, b_p2[dd]);
    } else if (tid < 128) {
        const int dd = tid - 96;
        float s = 0.f;
        #pragma unroll
        for (int k = 0; k < 32; k++) s = fmaf(s_acsum[k], w_c2[k * 32 + dd], s);
        s_pool[96 + dd] = fmaf(s, inv_len, b_c2[dd]);
    } else if (tid < 160) {
        const int dd = tid - 128;
        float e = 0.f;
        #pragma unroll
        for (int v = 0; v < 34; v++) e = fmaf((float)s_hist[H_REP + v], erep[v * 32 + dd], e);
        s_rep[dd] = e;
    }
    __syncthreads();

    if (tid < 32) {
        s_pool[tid] = (e1 + s_rep[tid]) * (inv_len * 0.2f);
    }
    __syncthreads();

    // ---- fused head fc1 (128->64): warp = (d-chunk, j-half); COALESCED w_fc1 reads ----
    {
        const int dc = w >> 1;                 // 0..3: d-chunk of 32
        const int j = ((w & 1) << 5) + lane;   // 0..63 output col
        const float* wp = w_fc1 + (dc * 32) * 64 + j;
        float s = 0.f;
        #pragma unroll
        for (int i = 0; i < 32; i++)
            s = fmaf(s_pool[dc * 32 + i], wp[i * 64], s);
        s_part[dc][j] = s;
    }
    __syncthreads();

    if (tid < 64) {
        float h = b_fc1[tid] + ((s_part[0][tid] + s_part[1][tid]) +
                                (s_part[2][tid] + s_part[3][tid]));
        s_h1[tid] = fmaxf(h, 0.f);
    }
    __syncthreads();

    // ---- fc2 (64->2, relu): warp 0 -> out0, warp 1 -> out1, warp reduce ----
    if (tid < 64) {
        const int o = w;   // 0 or 1
        float s = fmaf(s_h1[lane], w_fc2[lane * 2 + o],
                       s_h1[lane + 32] * w_fc2[(lane + 32) * 2 + o]);
        s += __shfl_xor_sync(0xffffffffu, s, 16);
        s += __shfl_xor_sync(0xffffffffu, s, 8);
        s += __shfl_xor_sync(0xffffffffu, s, 4);
        s += __shfl_xor_sync(0xffffffffu, s, 2);
        s += __shfl_xor_sync(0xffffffffu, s, 1);
        if (lane == 0) out[b * 2 + o] = fmaxf(s + b_fc2[o], 0.f);
    }
}

extern "C" void kernel_launch(void* const* d_in, const int* in_sizes, int n_in,
                              void* d_out, int out_size)
{
    const float* cont_p = (const float*)d_in[0];
    const float* cont_c = (const float*)d_in[1];
    const int*   cat_p  = (const int*)d_in[2];
    const int*   cat_c  = (const int*)d_in[3];
    const int*   lengths= (const int*)d_in[4];
    const float* w_p1   = (const float*)d_in[5];
    const float* b_p1   = (const float*)d_in[6];
    const float* w_p2   = (const float*)d_in[7];
    const float* b_p2   = (const float*)d_in[8];
    const float* w_c1   = (const float*)d_in[9];
    const float* b_c1   = (const float*)d_in[10];
    const float* w_c2   = (const float*)d_in[11];
    const float* b_c2   = (const float*)d_in[12];
    const float* eg     = (const float*)d_in[13];
    const float* ek     = (const float*)d_in[14];
    const float* epr    = (const float*)d_in[15];
    const float* ejob   = (const float*)d_in[16];
    const float* erep   = (const float*)d_in[17];
    const float* epl    = (const float*)d_in[18];
    const float* eadd   = (const float*)d_in[19];
    const float* w_fc1  = (const float*)d_in[20];
    const float* b_fc1  = (const float*)d_in[21];
    const float* w_fc2  = (const float*)d_in[22];
    const float* b_fc2  = (const float*)d_in[23];
    float* out = (float*)d_out;

    fused_kernel<<<NB, 256>>>(cont_p, cont_c, cat_p, cat_c, lengths,
                              w_p1, b_p1, w_p2, b_p2, w_c1, b_c1, w_c2, b_c2,
                              eg, ek, epr, ejob, erep, epl, eadd,
                              w_fc1, b_fc1, w_fc2, b_fc2, out);
}